// round 7
// baseline (speedup 1.0000x reference)
#include <cuda_runtime.h>
#include <cstdint>

// Problem constants
#define BATCH 16
#define CCH   512
#define NPIX  4096          // 64*64
#define NHEAD 8
#define HDIM  64
#define EPS   1e-6f

// Tensor-core GEMM tile config
#define BMT 128
#define BNT 128
#define BKT 32

// Scratch (device globals - no allocation at launch time).
__device__ float g_QK[(size_t)BATCH * 1024 * NPIX];   // relu(w_qk @ (x+pos)): q = ch 0..511, k = ch 512..1023
__device__ float g_V [(size_t)BATCH * CCH  * NPIX];   // V, then attention output (reused)
__device__ float g_KV[(size_t)BATCH * NHEAD * 65 * 64];

// ---------------------------------------------------------------------------
// tf32 helpers
// ---------------------------------------------------------------------------
__device__ __forceinline__ uint32_t f2tf32(float f) {
    uint32_t r;
    asm("cvt.rna.tf32.f32 %0, %1;" : "=r"(r) : "f"(f));
    return r;
}

__device__ __forceinline__ void mma_tf32(
    float& c0, float& c1, float& c2, float& c3,
    uint32_t a0, uint32_t a1, uint32_t a2, uint32_t a3,
    uint32_t b0, uint32_t b1)
{
    asm volatile(
        "mma.sync.aligned.m16n8k8.row.col.f32.tf32.tf32.f32 "
        "{%0,%1,%2,%3}, {%4,%5,%6,%7}, {%8,%9}, {%0,%1,%2,%3};"
        : "+f"(c0), "+f"(c1), "+f"(c2), "+f"(c3)
        : "r"(a0), "r"(a1), "r"(a2), "r"(a3), "r"(b0), "r"(b1));
}

// ---------------------------------------------------------------------------
// Fragment-packed smem layout.
// A: [mt(8)][ks(4)][lane(33 pad)][reg(4)]  -> consumer does one LDS.128
// B: [nt(16)][ks(4)][lane(33 pad)][reg(2)] -> consumer does one LDS.64
//    (with lane XOR-swizzle on (nt>>2)&3 to break producer bank conflicts)
// ---------------------------------------------------------------------------
#define A_STAGE (8 * 4 * 33 * 4)    // 4224 words
#define B_STAGE (16 * 4 * 33 * 2)   // 4224 words
#define SMEM_WORDS (2 * (A_STAGE + B_STAGE))   // 16896 words = 67584 B

__device__ __forceinline__ int a_idx(int mt, int ks, int lane, int reg) {
    return ((mt * 4 + ks) * 33 + lane) * 4 + reg;
}
__device__ __forceinline__ int b_idx(int nt, int ks, int lane, int reg) {
    return ((nt * 4 + ks) * 33 + lane) * 2 + reg;
}
__device__ __forceinline__ int b_swz(int nt, int lane) {
    return lane ^ (((nt >> 2) & 3) << 2);
}

// ---------------------------------------------------------------------------
// Tensor-core batched GEMM: C[b] (MxN) = A (MxK shared weights) * X[b] (KxN)
// 256 threads, 128x128x32 tiles, double-buffered fragment-packed smem.
// 8 warps (4x2); warp computes 32x64 via m16n8k8 tf32 mma.
// ---------------------------------------------------------------------------
template<bool FUSE_ADD, bool RELU>
__device__ __forceinline__ void gemm_tc_body(
    const float* __restrict__ A,
    const float* __restrict__ X0,
    const float* __restrict__ X1,
    float* __restrict__ C,
    int M, int K, int N)
{
    extern __shared__ uint32_t smem[];
    uint32_t* Af = smem;                    // 2 stages of A fragments
    uint32_t* Bf = smem + 2 * A_STAGE;      // 2 stages of B fragments

    const int b = blockIdx.z;
    const float* X0b = X0 + (size_t)b * K * N;
    const float* X1b = FUSE_ADD ? (X1 + (size_t)b * K * N) : nullptr;
    float* Cb = C + (size_t)b * M * N;

    const int tileM = blockIdx.y * BMT;
    const int tileN = blockIdx.x * BNT;

    const int tid   = threadIdx.x;
    const int warp  = tid >> 5;
    const int lane  = tid & 31;
    const int group = lane >> 2;
    const int tig   = lane & 3;
    const int warp_m = warp >> 1;          // 0..3 -> m16 tiles 2wm, 2wm+1
    const int warp_n = warp & 1;           // 0..1 -> n8 tiles 8wn..8wn+7

    float acc[2][8][4];
#pragma unroll
    for (int mt = 0; mt < 2; mt++)
#pragma unroll
        for (int nt = 0; nt < 8; nt++)
#pragma unroll
            for (int i = 0; i < 4; i++) acc[mt][nt][i] = 0.0f;

    float4 ar[4], xv[4];

    auto load_regs = [&](int k0) {
#pragma unroll
        for (int i = 0; i < 4; i++) {
            int f = tid + i * 256;         // 0..1023
            int arow = f >> 3, ac4 = f & 7;
            ar[i] = *(const float4*)(A + (size_t)(tileM + arow) * K + k0 + ac4 * 4);
            int krow = f >> 5, n4 = f & 31;
            size_t off = (size_t)(k0 + krow) * N + tileN + n4 * 4;
            float4 v = *(const float4*)(X0b + off);
            if (FUSE_ADD) {
                float4 p = *(const float4*)(X1b + off);
                v.x += p.x; v.y += p.y; v.z += p.z; v.w += p.w;
            }
            xv[i] = v;
        }
    };

    auto store_smem = [&](int stage) {
        uint32_t* As = Af + stage * A_STAGE;
        uint32_t* Bs = Bf + stage * B_STAGE;
#pragma unroll
        for (int i = 0; i < 4; i++) {
            int f = tid + i * 256;
            // ---- A fragment scatter ----
            {
                int arow = f >> 3, ac4 = f & 7;
                int mt = arow >> 4, rm = arow & 15;
                int ks = ac4 >> 1;
                int reg = (rm >> 3) + 2 * (ac4 & 1);
                int lb = (rm & 7) << 2;
                float v[4] = {ar[i].x, ar[i].y, ar[i].z, ar[i].w};
#pragma unroll
                for (int j = 0; j < 4; j++)
                    As[a_idx(mt, ks, lb + j, reg)] = f2tf32(v[j]);
            }
            // ---- B fragment scatter ----
            {
                int krow = f >> 5, n4 = f & 31;
                int ks = krow >> 3, k7 = krow & 7;
                int nt = n4 >> 1;
                int reg = k7 >> 2, k3 = k7 & 3;
                int nnb = (n4 & 1) * 4;
                float v[4] = {xv[i].x, xv[i].y, xv[i].z, xv[i].w};
#pragma unroll
                for (int j = 0; j < 4; j++) {
                    int ln = ((nnb + j) << 2) | k3;
                    Bs[b_idx(nt, ks, b_swz(nt, ln), reg)] = f2tf32(v[j]);
                }
            }
        }
    };

    auto compute = [&](int stage) {
        const uint32_t* As = Af + stage * A_STAGE;
        const uint32_t* Bs = Bf + stage * B_STAGE;
#pragma unroll
        for (int ks = 0; ks < 4; ks++) {
            uint4 af[2];
#pragma unroll
            for (int mt = 0; mt < 2; mt++)
                af[mt] = *(const uint4*)(As + a_idx(warp_m * 2 + mt, ks, lane, 0));
            uint2 bf[8];
#pragma unroll
            for (int nt = 0; nt < 8; nt++) {
                int gnt = warp_n * 8 + nt;
                bf[nt] = *(const uint2*)(Bs + b_idx(gnt, ks, b_swz(gnt, lane), 0));
            }
#pragma unroll
            for (int mt = 0; mt < 2; mt++)
#pragma unroll
                for (int nt = 0; nt < 8; nt++)
                    mma_tf32(acc[mt][nt][0], acc[mt][nt][1],
                             acc[mt][nt][2], acc[mt][nt][3],
                             af[mt].x, af[mt].y, af[mt].z, af[mt].w,
                             bf[nt].x, bf[nt].y);
        }
    };

    const int NK = K / BKT;   // 16
    load_regs(0);
    store_smem(0);
    __syncthreads();

#pragma unroll 1
    for (int t = 0; t < NK; t++) {
        if (t + 1 < NK) load_regs((t + 1) * BKT);
        compute(t & 1);
        if (t + 1 < NK) {
            store_smem((t + 1) & 1);
            __syncthreads();
        }
    }

    // ---- epilogue ----
#pragma unroll
    for (int mt = 0; mt < 2; mt++) {
        int r = tileM + warp_m * 32 + mt * 16 + group;
#pragma unroll
        for (int nt = 0; nt < 8; nt++) {
            int c = tileN + warp_n * 64 + nt * 8 + tig * 2;
            float2 v0, v1;
            v0.x = acc[mt][nt][0]; v0.y = acc[mt][nt][1];
            v1.x = acc[mt][nt][2]; v1.y = acc[mt][nt][3];
            if (RELU) {
                v0.x = fmaxf(v0.x, 0.0f); v0.y = fmaxf(v0.y, 0.0f);
                v1.x = fmaxf(v1.x, 0.0f); v1.y = fmaxf(v1.y, 0.0f);
            }
            *(float2*)(Cb + (size_t)r * N + c)       = v0;
            *(float2*)(Cb + (size_t)(r + 8) * N + c) = v1;
        }
    }
}

__global__ __launch_bounds__(256, 2) void gemm_qk(
    const float* __restrict__ A, const float* __restrict__ x,
    const float* __restrict__ pos)
{
    gemm_tc_body<true, true>(A, x, pos, g_QK, 1024, CCH, NPIX);
}

__global__ __launch_bounds__(256, 2) void gemm_v(
    const float* __restrict__ A, const float* __restrict__ x)
{
    gemm_tc_body<false, false>(A, x, nullptr, g_V, 512, CCH, NPIX);
}

__global__ __launch_bounds__(256, 2) void gemm_o(
    const float* __restrict__ A, float* __restrict__ out)
{
    gemm_tc_body<false, false>(A, g_V, nullptr, out, 512, CCH, NPIX);
}

// ---------------------------------------------------------------------------
// KV kernel (tensor-core), unchanged from R5.
// ---------------------------------------------------------------------------
#define KVS 68

__global__ __launch_bounds__(256) void kv_mma_kernel()
{
    const int bh = blockIdx.x;
    const int b = bh >> 3, h = bh & 7;
    const float* kp = g_QK + ((size_t)b * 1024 + 512 + h * 64) * NPIX;
    const float* vp = g_V  + ((size_t)b * 512  +       h * 64) * NPIX;

    __shared__ uint32_t Vs[80][KVS];
    __shared__ uint32_t Ks[64][KVS];

    const int tid  = threadIdx.x;
    const int warp = tid >> 5;
    const int lane = tid & 31;
    const int group = lane >> 2;
    const int tig   = lane & 3;

    for (int i = tid; i < 16 * KVS; i += 256) {
        int r = 64 + i / KVS, c = i % KVS;
        Vs[r][c] = (r == 64) ? __float_as_uint(1.0f) : 0u;
    }

    float acc[5][4];
#pragma unroll
    for (int mt = 0; mt < 5; mt++)
#pragma unroll
        for (int i = 0; i < 4; i++) acc[mt][i] = 0.0f;

    for (int n0 = 0; n0 < NPIX; n0 += 64) {
        __syncthreads();
#pragma unroll
        for (int i = 0; i < 4; i++) {
            int f = tid + i * 256;
            int row = f >> 4, c4 = f & 15;
            float4 v = *(const float4*)(vp + (size_t)row * NPIX + n0 + c4 * 4);
            uint4 vt;
            vt.x = f2tf32(v.x); vt.y = f2tf32(v.y); vt.z = f2tf32(v.z); vt.w = f2tf32(v.w);
            *(uint4*)(&Vs[row][c4 * 4]) = vt;
            float4 kk = *(const float4*)(kp + (size_t)row * NPIX + n0 + c4 * 4);
            uint4 kt;
            kt.x = f2tf32(kk.x); kt.y = f2tf32(kk.y); kt.z = f2tf32(kk.z); kt.w = f2tf32(kk.w);
            *(uint4*)(&Ks[row][c4 * 4]) = kt;
        }
        __syncthreads();

#pragma unroll
        for (int ks = 0; ks < 8; ks++) {
            const int k = ks * 8;
            uint32_t b0 = Ks[warp * 8 + group][k + tig];
            uint32_t b1 = Ks[warp * 8 + group][k + tig + 4];
#pragma unroll
            for (int mt = 0; mt < 5; mt++) {
                int r = mt * 16 + group;
                uint32_t a0 = Vs[r    ][k + tig];
                uint32_t a1 = Vs[r + 8][k + tig];
                uint32_t a2 = Vs[r    ][k + tig + 4];
                uint32_t a3 = Vs[r + 8][k + tig + 4];
                mma_tf32(acc[mt][0], acc[mt][1], acc[mt][2], acc[mt][3],
                         a0, a1, a2, a3, b0, b1);
            }
        }
    }

    float* kvb = g_KV + (size_t)bh * 65 * 64;
#pragma unroll
    for (int mt = 0; mt < 5; mt++) {
        int r0 = mt * 16 + group;
        int r1 = r0 + 8;
        int c = warp * 8 + tig * 2;
        if (r0 < 65) {
            kvb[r0 * 64 + c]     = acc[mt][0];
            kvb[r0 * 64 + c + 1] = acc[mt][1];
        }
        if (r1 < 65) {
            kvb[r1 * 64 + c]     = acc[mt][2];
            kvb[r1 * 64 + c + 1] = acc[mt][3];
        }
    }
}

// ---------------------------------------------------------------------------
// Attention output (tensor-core), unchanged from R5.
// ---------------------------------------------------------------------------
#define QS 136

__global__ __launch_bounds__(256) void attn_mma_kernel()
{
    const int bh = blockIdx.y;
    const int b = bh >> 3, h = bh & 7;
    const int ntile = blockIdx.x * 128;

    __shared__ uint32_t As[80][KVS];
    __shared__ uint32_t Qs[64][QS];
    __shared__ float norms[8][16];

    const int tid  = threadIdx.x;
    const int warp = tid >> 5;
    const int lane = tid & 31;
    const int group = lane >> 2;
    const int tig   = lane & 3;

    const float* kvb = g_KV + (size_t)bh * 65 * 64;
    for (int i = tid; i < 80 * 64; i += 256) {
        int r = i >> 6, c = i & 63;
        As[r][c] = (r < 65) ? f2tf32(kvb[i]) : 0u;
    }
    const float* q = g_QK + ((size_t)b * 1024 + h * 64) * NPIX + ntile;
#pragma unroll
    for (int i = 0; i < 8; i++) {
        int f = tid + i * 256;
        int row = f >> 5, c4 = f & 31;
        float4 v = *(const float4*)(q + (size_t)row * NPIX + c4 * 4);
        uint4 t;
        t.x = f2tf32(v.x); t.y = f2tf32(v.y); t.z = f2tf32(v.z); t.w = f2tf32(v.w);
        *(uint4*)(&Qs[row][c4 * 4]) = t;
    }
    __syncthreads();

    float acc[5][2][4];
#pragma unroll
    for (int mt = 0; mt < 5; mt++)
#pragma unroll
        for (int nt = 0; nt < 2; nt++)
#pragma unroll
            for (int i = 0; i < 4; i++) acc[mt][nt][i] = 0.0f;

#pragma unroll
    for (int ks = 0; ks < 8; ks++) {
        const int k = ks * 8;
        uint32_t bf[2][2];
#pragma unroll
        for (int nt = 0; nt < 2; nt++) {
            int c = warp * 16 + nt * 8 + group;
            bf[nt][0] = Qs[k + tig    ][c];
            bf[nt][1] = Qs[k + tig + 4][c];
        }
#pragma unroll
        for (int mt = 0; mt < 5; mt++) {
            int r = mt * 16 + group;
            uint32_t a0 = As[r    ][k + tig];
            uint32_t a1 = As[r + 8][k + tig];
            uint32_t a2 = As[r    ][k + tig + 4];
            uint32_t a3 = As[r + 8][k + tig + 4];
#pragma unroll
            for (int nt = 0; nt < 2; nt++)
                mma_tf32(acc[mt][nt][0], acc[mt][nt][1],
                         acc[mt][nt][2], acc[mt][nt][3],
                         a0, a1, a2, a3, bf[nt][0], bf[nt][1]);
        }
    }

    if (group == 0) {
#pragma unroll
        for (int nt = 0; nt < 2; nt++) {
            norms[warp][nt * 8 + tig * 2]     = acc[4][nt][0];
            norms[warp][nt * 8 + tig * 2 + 1] = acc[4][nt][1];
        }
    }
    __syncwarp();

    float* ob = g_V + ((size_t)b * 512 + h * 64) * NPIX + ntile;
#pragma unroll
    for (int nt = 0; nt < 2; nt++) {
        int cl = nt * 8 + tig * 2;
        float inv0 = 1.0f / (norms[warp][cl]     + EPS);
        float inv1 = 1.0f / (norms[warp][cl + 1] + EPS);
        int c = warp * 16 + cl;
#pragma unroll
        for (int mt = 0; mt < 4; mt++) {
            int r0 = mt * 16 + group;
            float2 v0, v1;
            v0.x = acc[mt][nt][0] * inv0; v0.y = acc[mt][nt][1] * inv1;
            v1.x = acc[mt][nt][2] * inv0; v1.y = acc[mt][nt][3] * inv1;
            *(float2*)(ob + (size_t)r0 * NPIX + c)       = v0;
            *(float2*)(ob + (size_t)(r0 + 8) * NPIX + c) = v1;
        }
    }
}

// ---------------------------------------------------------------------------
extern "C" void kernel_launch(void* const* d_in, const int* in_sizes, int n_in,
                              void* d_out, int out_size)
{
    const float* x    = (const float*)d_in[0];
    const float* pos  = (const float*)d_in[1];
    const float* w_qk = (const float*)d_in[2];
    const float* w_v  = (const float*)d_in[3];
    const float* w_o  = (const float*)d_in[4];
    float* out = (float*)d_out;

    const int smem_bytes = SMEM_WORDS * 4;   // 67584
    static bool attr_done = false;
    if (!attr_done) {
        cudaFuncSetAttribute(gemm_qk, cudaFuncAttributeMaxDynamicSharedMemorySize, smem_bytes);
        cudaFuncSetAttribute(gemm_v,  cudaFuncAttributeMaxDynamicSharedMemorySize, smem_bytes);
        cudaFuncSetAttribute(gemm_o,  cudaFuncAttributeMaxDynamicSharedMemorySize, smem_bytes);
        attr_done = true;
    }

    dim3 thr(256);

    // 1) qk = relu(w_qk @ (x+pos))   [B,1024,N]
    gemm_qk<<<dim3(NPIX / BNT, 1024 / BMT, BATCH), thr, smem_bytes>>>(w_qk, x, pos);

    // 2) v = w_v @ x                 [B,512,N]
    gemm_v<<<dim3(NPIX / BNT, 512 / BMT, BATCH), thr, smem_bytes>>>(w_v, x);

    // 3) kv = v_pad @ k^T            [B,H,65,64]
    kv_mma_kernel<<<BATCH * NHEAD, 256>>>();

    // 4) out = normalize(kv @ q)     [B,512,N]  in-place over g_V
    attn_mma_kernel<<<dim3(NPIX / 128, BATCH * NHEAD), 256>>>();

    // 5) final = w_o @ out           [B,512,N]
    gemm_o<<<dim3(NPIX / BNT, 512 / BMT, BATCH), thr, smem_bytes>>>(w_o, out);
}